// round 3
// baseline (speedup 1.0000x reference)
#include <cuda_runtime.h>
#include <cstdint>

#define S_TOK 8192
#define MDIM  1024
#define EEXP  8
#define HDIM  2048
#define CCAP  2048
#define BB    4
#define TT    2048

// ---------------- scratch (device globals; no allocations allowed) ----------
__device__ int   g_e0[S_TOK], g_e1[S_TOK];
__device__ float g_g0[S_TOK], g_g1[S_TOK];
__device__ int   g_pos0[S_TOK], g_pos1[S_TOK];
__device__ int   g_tok[EEXP * CCAP];
__device__ int   g_ne[EEXP];
__device__ float g_w2sum[EEXP * HDIM];
__device__ float g_b2sum[EEXP];
__device__ float g_z[EEXP * CCAP];
__device__ float g_outsum[S_TOK];

// ---------------- routing: warp per token ----------------------------------
__global__ __launch_bounds__(256) void route_kernel(const float* __restrict__ x,
                                                    const float* __restrict__ wg) {
    int gwarp = (blockIdx.x * blockDim.x + threadIdx.x) >> 5;
    int lane  = threadIdx.x & 31;
    if (gwarp >= S_TOK) return;
    const float* xr = x + (size_t)gwarp * MDIM;

    float acc[8];
#pragma unroll
    for (int e = 0; e < 8; e++) acc[e] = 0.f;

    for (int k = lane; k < MDIM; k += 32) {
        float xv = xr[k];
        const float4* w4 = (const float4*)(wg + (size_t)k * EEXP);
        float4 a = w4[0], b = w4[1];
        acc[0] += xv * a.x; acc[1] += xv * a.y; acc[2] += xv * a.z; acc[3] += xv * a.w;
        acc[4] += xv * b.x; acc[5] += xv * b.y; acc[6] += xv * b.z; acc[7] += xv * b.w;
    }
#pragma unroll
    for (int e = 0; e < 8; e++) {
#pragma unroll
        for (int o = 16; o; o >>= 1) acc[e] += __shfl_xor_sync(0xffffffffu, acc[e], o);
    }
    if (lane == 0) {
        float mx = acc[0];
#pragma unroll
        for (int e = 1; e < 8; e++) mx = fmaxf(mx, acc[e]);
        float p[8]; float den = 0.f;
#pragma unroll
        for (int e = 0; e < 8; e++) { p[e] = expf(acc[e] - mx); den += p[e]; }
#pragma unroll
        for (int e = 0; e < 8; e++) p[e] /= den;
        // top-2, lowest-index-first on ties (matches jax.lax.top_k)
        int i0 = 0; float v0 = p[0];
#pragma unroll
        for (int e = 1; e < 8; e++) if (p[e] > v0) { v0 = p[e]; i0 = e; }
        int i1 = -1; float v1 = -1.f;
#pragma unroll
        for (int e = 0; e < 8; e++) if (e != i0 && p[e] > v1) { v1 = p[e]; i1 = e; }
        float gden = v0 + v1 + 1e-9f;
        g_e0[gwarp] = i0;  g_e1[gwarp] = i1;
        g_g0[gwarp] = v0 / gden;  g_g1[gwarp] = v1 / gden;
    }
}

// ---------------- w2 row-sum: warp per (e,h) row ----------------------------
__global__ __launch_bounds__(256) void w2sum_kernel(const float* __restrict__ w2) {
    int row  = (blockIdx.x * blockDim.x + threadIdx.x) >> 5;
    int lane = threadIdx.x & 31;
    if (row >= EEXP * HDIM) return;
    const float* p = w2 + (size_t)row * MDIM;
    float s = 0.f;
    for (int m = lane; m < MDIM; m += 32) s += p[m];
#pragma unroll
    for (int o = 16; o; o >>= 1) s += __shfl_xor_sync(0xffffffffu, s, o);
    if (lane == 0) g_w2sum[row] = s;
}

__global__ void b2sum_kernel(const float* __restrict__ b2) {
    int warp = threadIdx.x >> 5, lane = threadIdx.x & 31;
    if (warp < EEXP) {
        float s = 0.f;
        for (int m = lane; m < MDIM; m += 32) s += b2[warp * MDIM + m];
#pragma unroll
        for (int o = 16; o; o >>= 1) s += __shfl_xor_sync(0xffffffffu, s, o);
        if (lane == 0) g_b2sum[warp] = s;
    }
}

// ---------------- ordered rank / capacity scan (single block) ---------------
__global__ __launch_bounds__(256) void scan_kernel() {
    __shared__ int cnt0[EEXP];
    __shared__ int running[16];     // cat = j*8 + e
    __shared__ int wcnt[8][16];
    int tid = threadIdx.x, lane = tid & 31, warp = tid >> 5;

    if (tid < EEXP) cnt0[tid] = 0;
    __syncthreads();
    // pass 1: full j=0 counts (needed for j=1 offsets)
    int local[8] = {0,0,0,0,0,0,0,0};
    for (int s = tid; s < S_TOK; s += 256) {
        int e = g_e0[s];
#pragma unroll
        for (int q = 0; q < 8; q++) local[q] += (e == q);
    }
#pragma unroll
    for (int q = 0; q < 8; q++) if (local[q]) atomicAdd(&cnt0[q], local[q]);
    __syncthreads();
    if (tid < EEXP) { running[tid] = 0; running[8 + tid] = cnt0[tid]; }
    __syncthreads();

    // pass 2: ordered ranks, chunked (token order preserved)
    for (int base = 0; base < S_TOK; base += 256) {
        int s  = base + tid;
        int e0 = g_e0[s], e1 = g_e1[s];
        if (tid < 128) wcnt[tid >> 4][tid & 15] = 0;
        __syncthreads();

        unsigned lt = (1u << lane) - 1u;
        unsigned m0 = __match_any_sync(0xffffffffu, e0);
        int r0 = __popc(m0 & lt);
        if ((m0 & lt) == 0) wcnt[warp][e0] = __popc(m0);
        unsigned m1 = __match_any_sync(0xffffffffu, e1);
        int r1 = __popc(m1 & lt);
        if ((m1 & lt) == 0) wcnt[warp][8 + e1] = __popc(m1);
        __syncthreads();

        int off0 = running[e0];
        int off1 = running[8 + e1];
#pragma unroll
        for (int w = 0; w < 8; w++) {
            if (w < warp) { off0 += wcnt[w][e0]; off1 += wcnt[w][8 + e1]; }
        }
        int pos0 = off0 + r0;
        int pos1 = off1 + r1;
        if (pos0 < CCAP) { g_pos0[s] = pos0; g_tok[e0 * CCAP + pos0] = s; } else g_pos0[s] = -1;
        if (pos1 < CCAP) { g_pos1[s] = pos1; g_tok[e1 * CCAP + pos1] = s; } else g_pos1[s] = -1;
        __syncthreads();
        if (tid < 16) {
            int t = 0;
#pragma unroll
            for (int w = 0; w < 8; w++) t += wcnt[w][tid];
            running[tid] += t;
        }
        __syncthreads();
    }
    if (tid < EEXP) g_ne[tid] = min(running[8 + tid], CCAP);
}

// ---------------- zero z accumulators ---------------------------------------
__global__ void zero_z_kernel() {
    int i = blockIdx.x * blockDim.x + threadIdx.x;
    if (i < EEXP * CCAP) g_z[i] = 0.f;
}

// ---------------- FFN: z[e,c] = relu(x[tok] @ w1[e] + b1[e]) . w2sum[e] -----
#define TC 64
#define TH 64
#define TKK 16

__global__ __launch_bounds__(256) void ffn_kernel(const float* __restrict__ x,
                                                  const float* __restrict__ w1,
                                                  const float* __restrict__ b1) {
    int h0    = blockIdx.x * TH;
    int ctile = blockIdx.y;
    int e     = ctile >> 5;              // 2048/64 = 32 c-tiles per expert
    int c0    = (ctile & 31) * TC;
    int ne    = g_ne[e];
    if (c0 >= ne) return;

    int tid = threadIdx.x;
    int tx  = tid & 15, ty = tid >> 4;

    __shared__ __align__(16) float As[TKK][TC + 4];   // +4 pad keeps 16B align, kills store conflicts
    __shared__ __align__(16) float Bs[TKK][TH];
    __shared__ int   stok[TC];
    __shared__ float red[TC][16];

    if (tid < TC) {
        int c = c0 + tid;
        stok[tid] = (c < ne) ? g_tok[e * CCAP + c] : -1;
    }
    __syncthreads();

    float acc[4][4];
#pragma unroll
    for (int i = 0; i < 4; i++)
#pragma unroll
        for (int j = 0; j < 4; j++) acc[i][j] = 0.f;

    const float* wb = w1 + (size_t)e * MDIM * HDIM + h0;

    for (int k0 = 0; k0 < MDIM; k0 += TKK) {
#pragma unroll
        for (int i = 0; i < 4; i++) {
            int idx = tid + i * 256;
            int r = idx >> 4, kk = idx & 15;
            int t = stok[r];
            As[kk][r] = (t >= 0) ? x[(size_t)t * MDIM + k0 + kk] : 0.f;
        }
#pragma unroll
        for (int i = 0; i < 4; i++) {
            int idx = tid + i * 256;
            int kk = idx >> 6, hh = idx & 63;
            Bs[kk][hh] = wb[(size_t)(k0 + kk) * HDIM + hh];
        }
        __syncthreads();
#pragma unroll
        for (int kk = 0; kk < TKK; kk++) {
            float4 a = *(const float4*)&As[kk][ty * 4];
            float4 b = *(const float4*)&Bs[kk][tx * 4];
            acc[0][0] += a.x * b.x; acc[0][1] += a.x * b.y; acc[0][2] += a.x * b.z; acc[0][3] += a.x * b.w;
            acc[1][0] += a.y * b.x; acc[1][1] += a.y * b.y; acc[1][2] += a.y * b.z; acc[1][3] += a.y * b.w;
            acc[2][0] += a.z * b.x; acc[2][1] += a.z * b.y; acc[2][2] += a.z * b.z; acc[2][3] += a.z * b.w;
            acc[3][0] += a.w * b.x; acc[3][1] += a.w * b.y; acc[3][2] += a.w * b.z; acc[3][3] += a.w * b.w;
        }
        __syncthreads();
    }

    // epilogue: relu(+b1) . w2sum, reduce over h within tile
    float b1v[4], wsv[4];
#pragma unroll
    for (int j = 0; j < 4; j++) {
        int h = h0 + tx * 4 + j;
        b1v[j] = b1[e * HDIM + h];
        wsv[j] = g_w2sum[e * HDIM + h];
    }
#pragma unroll
    for (int i = 0; i < 4; i++) {
        float zp = 0.f;
#pragma unroll
        for (int j = 0; j < 4; j++) {
            float hv = acc[i][j] + b1v[j];
            if (hv > 0.f) zp += hv * wsv[j];
        }
        red[ty * 4 + i][tx] = zp;
    }
    __syncthreads();
    if (tid < TC) {
        int c = c0 + tid;
        if (c < ne) {
            float sum = 0.f;
#pragma unroll
            for (int t = 0; t < 16; t++) sum += red[tid][t];
            atomicAdd(&g_z[e * CCAP + c], sum);
        }
    }
}

// ---------------- combine per token (no atomics) ----------------------------
__global__ void combine_kernel() {
    int s = blockIdx.x * blockDim.x + threadIdx.x;
    if (s >= S_TOK) return;
    float v = 0.f;
    int p0 = g_pos0[s];
    if (p0 >= 0) { int e = g_e0[s]; v += g_g0[s] * (g_z[e * CCAP + p0] + g_b2sum[e]); }
    int p1 = g_pos1[s];
    if (p1 >= 0) { int e = g_e1[s]; v += g_g1[s] * (g_z[e * CCAP + p1] + g_b2sum[e]); }
    g_outsum[s] = v;
}

// ---------------- per-batch log_softmax over T ------------------------------
__global__ __launch_bounds__(256) void lsm_kernel(float* __restrict__ out) {
    int b = blockIdx.x, tid = threadIdx.x;
    __shared__ float sh[256];
    const float* v = g_outsum + b * TT;

    float mx = -3.4e38f;
    for (int t = tid; t < TT; t += 256) mx = fmaxf(mx, v[t]);
    sh[tid] = mx; __syncthreads();
    for (int o = 128; o; o >>= 1) { if (tid < o) sh[tid] = fmaxf(sh[tid], sh[tid + o]); __syncthreads(); }
    mx = sh[0]; __syncthreads();

    float sum = 0.f;
    for (int t = tid; t < TT; t += 256) sum += expf(v[t] - mx);
    sh[tid] = sum; __syncthreads();
    for (int o = 128; o; o >>= 1) { if (tid < o) sh[tid] += sh[tid + o]; __syncthreads(); }
    float lse = logf(sh[0]);

    for (int t = tid; t < TT; t += 256) out[b * TT + t] = v[t] - mx - lse;
}

// ---------------- launch -----------------------------------------------------
extern "C" void kernel_launch(void* const* d_in, const int* in_sizes, int n_in,
                              void* d_out, int out_size) {
    const float* x  = (const float*)d_in[0];
    const float* wg = (const float*)d_in[1];
    const float* w1 = (const float*)d_in[2];
    const float* b1 = (const float*)d_in[3];
    const float* w2 = (const float*)d_in[4];
    const float* b2 = (const float*)d_in[5];
    float* out = (float*)d_out;

    route_kernel<<<S_TOK / 8, 256>>>(x, wg);
    w2sum_kernel<<<(EEXP * HDIM) / 8, 256>>>(w2);
    b2sum_kernel<<<1, 256>>>(b2);
    scan_kernel<<<1, 256>>>();
    zero_z_kernel<<<(EEXP * CCAP) / 256, 256>>>();

    dim3 g(HDIM / TH, (EEXP * CCAP) / TC);
    ffn_kernel<<<g, 256>>>(x, w1, b1);

    combine_kernel<<<S_TOK / 256, 256>>>();
    lsm_kernel<<<BB, 256>>>(out);
}

// round 7
// speedup vs baseline: 2.8651x; 2.8651x over previous
#include <cuda_runtime.h>
#include <cuda_bf16.h>
#include <cstdint>

#define S_TOK 8192
#define MDIM  1024
#define EEXP  8
#define HDIM  2048
#define CCAP  2048
#define BB    4
#define TT    2048

// ---------------- scratch (device globals; no allocations allowed) ----------
__device__ int   g_e0[S_TOK], g_e1[S_TOK];
__device__ float g_g0[S_TOK], g_g1[S_TOK];
__device__ int   g_pos0[S_TOK], g_pos1[S_TOK];
__device__ int   g_tok[EEXP * CCAP];
__device__ int   g_ne[EEXP];
__device__ float g_w2sum[EEXP * HDIM];
__device__ float g_b2sum[EEXP];
__device__ float g_z[EEXP * CCAP];
__device__ float g_outsum[S_TOK];
// bf16 split operands
__device__ __nv_bfloat16 g_xhi[S_TOK * MDIM];
__device__ __nv_bfloat16 g_xlo[S_TOK * MDIM];
__device__ __nv_bfloat16 g_w1hi[EEXP * HDIM * MDIM];   // transposed: [e][h][m]
__device__ __nv_bfloat16 g_w1lo[EEXP * HDIM * MDIM];

// ---------------- PTX helpers (family-portable only) -------------------------
__device__ __forceinline__ uint32_t smem_u32(const void* p) {
    uint32_t a;
    asm("{ .reg .u64 t; cvta.to.shared.u64 t, %1; cvt.u32.u64 %0, t; }" : "=r"(a) : "l"(p));
    return a;
}
__device__ __forceinline__ void ldsm4(uint32_t* r, uint32_t addr) {
    asm volatile("ldmatrix.sync.aligned.m8n8.x4.shared.b16 {%0,%1,%2,%3}, [%4];"
                 : "=r"(r[0]), "=r"(r[1]), "=r"(r[2]), "=r"(r[3]) : "r"(addr));
}
__device__ __forceinline__ void mma16816(float* c, const uint32_t* a, const uint32_t* b) {
    asm volatile("mma.sync.aligned.m16n8k16.row.col.f32.bf16.bf16.f32 "
                 "{%0,%1,%2,%3}, {%4,%5,%6,%7}, {%8,%9}, {%0,%1,%2,%3};"
                 : "+f"(c[0]), "+f"(c[1]), "+f"(c[2]), "+f"(c[3])
                 : "r"(a[0]), "r"(a[1]), "r"(a[2]), "r"(a[3]), "r"(b[0]), "r"(b[1]));
}
#define CP_ASYNC16(dst, src, sz) \
    asm volatile("cp.async.cg.shared.global [%0], [%1], 16, %2;" :: "r"(dst), "l"(src), "r"(sz) : "memory")
#define CP_COMMIT() asm volatile("cp.async.commit_group;" ::: "memory")
#define CP_WAIT2()  asm volatile("cp.async.wait_group 2;" ::: "memory")

// ---------------- routing: warp per token ----------------------------------
__global__ __launch_bounds__(256) void route_kernel(const float* __restrict__ x,
                                                    const float* __restrict__ wg) {
    int gwarp = (blockIdx.x * blockDim.x + threadIdx.x) >> 5;
    int lane  = threadIdx.x & 31;
    if (gwarp >= S_TOK) return;
    const float* xr = x + (size_t)gwarp * MDIM;
    float acc[8];
#pragma unroll
    for (int e = 0; e < 8; e++) acc[e] = 0.f;
    for (int k = lane; k < MDIM; k += 32) {
        float xv = xr[k];
        const float4* w4 = (const float4*)(wg + (size_t)k * EEXP);
        float4 a = w4[0], b = w4[1];
        acc[0] += xv * a.x; acc[1] += xv * a.y; acc[2] += xv * a.z; acc[3] += xv * a.w;
        acc[4] += xv * b.x; acc[5] += xv * b.y; acc[6] += xv * b.z; acc[7] += xv * b.w;
    }
#pragma unroll
    for (int e = 0; e < 8; e++) {
#pragma unroll
        for (int o = 16; o; o >>= 1) acc[e] += __shfl_xor_sync(0xffffffffu, acc[e], o);
    }
    if (lane == 0) {
        float mx = acc[0];
#pragma unroll
        for (int e = 1; e < 8; e++) mx = fmaxf(mx, acc[e]);
        float p[8]; float den = 0.f;
#pragma unroll
        for (int e = 0; e < 8; e++) { p[e] = expf(acc[e] - mx); den += p[e]; }
#pragma unroll
        for (int e = 0; e < 8; e++) p[e] /= den;
        int i0 = 0; float v0 = p[0];
#pragma unroll
        for (int e = 1; e < 8; e++) if (p[e] > v0) { v0 = p[e]; i0 = e; }
        int i1 = -1; float v1 = -1.f;
#pragma unroll
        for (int e = 0; e < 8; e++) if (e != i0 && p[e] > v1) { v1 = p[e]; i1 = e; }
        float gden = v0 + v1 + 1e-9f;
        g_e0[gwarp] = i0;  g_e1[gwarp] = i1;
        g_g0[gwarp] = v0 / gden;  g_g1[gwarp] = v1 / gden;
    }
}

// ---------------- x -> bf16 hi/lo -------------------------------------------
__global__ __launch_bounds__(256) void cvt_x_kernel(const float* __restrict__ x) {
    int i = blockIdx.x * blockDim.x + threadIdx.x;
    if (i >= S_TOK * MDIM / 4) return;
    float4 v = ((const float4*)x)[i];
    __nv_bfloat16 h0 = __float2bfloat16(v.x), h1 = __float2bfloat16(v.y);
    __nv_bfloat16 h2 = __float2bfloat16(v.z), h3 = __float2bfloat16(v.w);
    __nv_bfloat16 l0 = __float2bfloat16(v.x - __bfloat162float(h0));
    __nv_bfloat16 l1 = __float2bfloat16(v.y - __bfloat162float(h1));
    __nv_bfloat16 l2 = __float2bfloat16(v.z - __bfloat162float(h2));
    __nv_bfloat16 l3 = __float2bfloat16(v.w - __bfloat162float(h3));
    __nv_bfloat162* ph = (__nv_bfloat162*)g_xhi;
    __nv_bfloat162* pl = (__nv_bfloat162*)g_xlo;
    ph[2*i]   = __nv_bfloat162(h0, h1); ph[2*i+1] = __nv_bfloat162(h2, h3);
    pl[2*i]   = __nv_bfloat162(l0, l1); pl[2*i+1] = __nv_bfloat162(l2, l3);
}

// ---------------- w1 transpose + bf16 hi/lo: (E,M,H) -> (E,H,M) -------------
__global__ __launch_bounds__(256) void cvt_w1t_kernel(const float* __restrict__ w1) {
    __shared__ float t[32][33];
    int e  = blockIdx.z;
    int h0 = blockIdx.x * 32, m0 = blockIdx.y * 32;
    int tx = threadIdx.x, ty = threadIdx.y;     // 32 x 8
#pragma unroll
    for (int i = 0; i < 4; i++)
        t[ty + 8*i][tx] = w1[((size_t)e * MDIM + (m0 + ty + 8*i)) * HDIM + h0 + tx];
    __syncthreads();
#pragma unroll
    for (int i = 0; i < 4; i++) {
        int h = h0 + ty + 8*i, m = m0 + tx;
        float v = t[tx][ty + 8*i];
        __nv_bfloat16 hi = __float2bfloat16(v);
        __nv_bfloat16 lo = __float2bfloat16(v - __bfloat162float(hi));
        size_t idx = ((size_t)e * HDIM + h) * MDIM + m;
        g_w1hi[idx] = hi;
        g_w1lo[idx] = lo;
    }
}

// ---------------- w2 row-sum -------------------------------------------------
__global__ __launch_bounds__(256) void w2sum_kernel(const float* __restrict__ w2) {
    int row  = (blockIdx.x * blockDim.x + threadIdx.x) >> 5;
    int lane = threadIdx.x & 31;
    if (row >= EEXP * HDIM) return;
    const float* p = w2 + (size_t)row * MDIM;
    float s = 0.f;
    for (int m = lane; m < MDIM; m += 32) s += p[m];
#pragma unroll
    for (int o = 16; o; o >>= 1) s += __shfl_xor_sync(0xffffffffu, s, o);
    if (lane == 0) g_w2sum[row] = s;
}

__global__ void b2sum_kernel(const float* __restrict__ b2) {
    int warp = threadIdx.x >> 5, lane = threadIdx.x & 31;
    if (warp < EEXP) {
        float s = 0.f;
        for (int m = lane; m < MDIM; m += 32) s += b2[warp * MDIM + m];
#pragma unroll
        for (int o = 16; o; o >>= 1) s += __shfl_xor_sync(0xffffffffu, s, o);
        if (lane == 0) g_b2sum[warp] = s;
    }
}

// ---------------- ordered rank / capacity scan (single block, 1024 thr) -----
__global__ __launch_bounds__(1024) void scan_kernel() {
    __shared__ int cnt0[EEXP];
    __shared__ int running[16];
    __shared__ int wcnt[32][16];
    int tid = threadIdx.x, lane = tid & 31, warp = tid >> 5;

    if (tid < EEXP) cnt0[tid] = 0;
    __syncthreads();
    int local[8] = {0,0,0,0,0,0,0,0};
    for (int s = tid; s < S_TOK; s += 1024) {
        int e = g_e0[s];
#pragma unroll
        for (int q = 0; q < 8; q++) local[q] += (e == q);
    }
#pragma unroll
    for (int q = 0; q < 8; q++) if (local[q]) atomicAdd(&cnt0[q], local[q]);
    __syncthreads();
    if (tid < EEXP) { running[tid] = 0; running[8 + tid] = cnt0[tid]; }
    __syncthreads();

    for (int base = 0; base < S_TOK; base += 1024) {
        int s  = base + tid;
        int e0 = g_e0[s], e1 = g_e1[s];
        if (tid < 512) wcnt[tid >> 4][tid & 15] = 0;
        __syncthreads();

        unsigned lt = (1u << lane) - 1u;
        unsigned m0 = __match_any_sync(0xffffffffu, e0);
        int r0 = __popc(m0 & lt);
        if ((m0 & lt) == 0) wcnt[warp][e0] = __popc(m0);
        unsigned m1 = __match_any_sync(0xffffffffu, e1);
        int r1 = __popc(m1 & lt);
        if ((m1 & lt) == 0) wcnt[warp][8 + e1] = __popc(m1);
        __syncthreads();

        int off0 = running[e0];
        int off1 = running[8 + e1];
#pragma unroll
        for (int w = 0; w < 32; w++) {
            if (w < warp) { off0 += wcnt[w][e0]; off1 += wcnt[w][8 + e1]; }
        }
        int pos0 = off0 + r0;
        int pos1 = off1 + r1;
        if (pos0 < CCAP) { g_pos0[s] = pos0; g_tok[e0 * CCAP + pos0] = s; } else g_pos0[s] = -1;
        if (pos1 < CCAP) { g_pos1[s] = pos1; g_tok[e1 * CCAP + pos1] = s; } else g_pos1[s] = -1;
        __syncthreads();
        if (tid < 16) {
            int t = 0;
#pragma unroll
            for (int w = 0; w < 32; w++) t += wcnt[w][tid];
            running[tid] += t;
        }
        __syncthreads();
    }
    if (tid < EEXP) g_ne[tid] = min(running[8 + tid], CCAP);
}

// ---------------- zero z -----------------------------------------------------
__global__ void zero_z_kernel() {
    int i = blockIdx.x * blockDim.x + threadIdx.x;
    if (i < EEXP * CCAP) g_z[i] = 0.f;
}

// ---------------- FFN via mma.sync bf16 (split 3-term) -----------------------
// CTA tile: 128 tokens x 128 H, BK = 32, 4-stage cp.async pipeline.
// Stage layout (bytes): Ahi [0,10240) Alo [10240,20480) Bhi [20480,30720) Blo [30720,40960)
// row stride 80 B (32 bf16 + 8 pad) -> ldmatrix conflict-free.
#define BKC      32
#define NCH      (MDIM / BKC)        // 32
#define ROWB     80
#define ARR_SZ   (128 * ROWB)        // 10240
#define STAGE_SZ (4 * ARR_SZ)        // 40960
#define NSTG     4
#define FFN_SMEM (NSTG * STAGE_SZ)   // 163840

__device__ __forceinline__ void ffn_load_chunk(int kc, uint32_t stage, const int* stok,
                                               int e, int h0, int tid) {
    int k0 = kc * BKC;
#pragma unroll
    for (int it = 0; it < 8; it++) {
        int id = tid + it * 256;
        int rem = id & 511;
        int row = rem >> 2, seg = rem & 3;
        uint32_t dst;
        const __nv_bfloat16* src;
        int sz = 16;
        if (id < 1024) {            // A
            int arr = id >> 9;
            int t = stok[row];
            const __nv_bfloat16* base = arr ? g_xlo : g_xhi;
            src = base + ((size_t)(t < 0 ? 0 : t) * MDIM + k0 + seg * 8);
            if (t < 0) sz = 0;
            dst = stage + arr * ARR_SZ + row * ROWB + seg * 16;
        } else {                    // B
            int arr = (id - 1024) >> 9;
            const __nv_bfloat16* base = arr ? g_w1lo : g_w1hi;
            src = base + ((size_t)(e * HDIM + h0 + row) * MDIM + k0 + seg * 8);
            dst = stage + 2 * ARR_SZ + arr * ARR_SZ + row * ROWB + seg * 16;
        }
        CP_ASYNC16(dst, src, sz);
    }
    CP_COMMIT();
}

__global__ __launch_bounds__(256, 1) void ffn_kernel(const float* __restrict__ b1) {
    extern __shared__ __align__(128) char smem[];
    __shared__ int stok[128];

    int h0 = blockIdx.x * 128;
    int e  = blockIdx.y >> 4;
    int c0 = (blockIdx.y & 15) * 128;
    int ne = g_ne[e];
    if (c0 >= ne) return;

    int tid = threadIdx.x, wid = tid >> 5, lane = tid & 31;
    int warpm = wid & 1, warpn = wid >> 1;   // 2 x 4 warp grid -> 64m x 32n per warp
    uint32_t sbase = smem_u32(smem);

    if (tid < 128) {
        int c = c0 + tid;
        stok[tid] = (c < ne) ? g_tok[e * CCAP + c] : -1;
    }
    __syncthreads();

    // prefetch 3 chunks
    ffn_load_chunk(0, sbase + 0 * STAGE_SZ, stok, e, h0, tid);
    ffn_load_chunk(1, sbase + 1 * STAGE_SZ, stok, e, h0, tid);
    ffn_load_chunk(2, sbase + 2 * STAGE_SZ, stok, e, h0, tid);

    float acc[4][4][4];
#pragma unroll
    for (int i = 0; i < 4; i++)
#pragma unroll
        for (int j = 0; j < 4; j++)
#pragma unroll
            for (int q = 0; q < 4; q++) acc[i][j][q] = 0.f;

    // per-lane ldmatrix offsets
    uint32_t aOff = (uint32_t)((warpm * 64 + (lane & 7) + (lane & 8)) * ROWB + ((lane >> 4) & 1) * 16);
    uint32_t bOff = (uint32_t)((warpn * 32 + (lane & 7) + ((lane >> 4) & 1) * 8) * ROWB + ((lane >> 3) & 1) * 16)
                  + 2 * ARR_SZ;

    for (int kc = 0; kc < NCH; kc++) {
        CP_WAIT2();
        __syncthreads();
        uint32_t stage = sbase + (uint32_t)(kc & (NSTG - 1)) * STAGE_SZ;
#pragma unroll
        for (int ks = 0; ks < 2; ks++) {
            uint32_t kadd = ks * 32;
            uint32_t ah[4][4], al[4][4], bh[8], bl[8];
#pragma unroll
            for (int mf = 0; mf < 4; mf++) {
                ldsm4(ah[mf], stage + aOff + mf * (16 * ROWB) + kadd);
                ldsm4(al[mf], stage + ARR_SZ + aOff + mf * (16 * ROWB) + kadd);
            }
#pragma unroll
            for (int np = 0; np < 2; np++) {
                ldsm4(bh + np * 4, stage + bOff + np * (16 * ROWB) + kadd);
                ldsm4(bl + np * 4, stage + ARR_SZ + bOff + np * (16 * ROWB) + kadd);
            }
#pragma unroll
            for (int mf = 0; mf < 4; mf++)
#pragma unroll
                for (int nf = 0; nf < 4; nf++) {
                    mma16816(acc[mf][nf], ah[mf], bh + nf * 2);
                    mma16816(acc[mf][nf], ah[mf], bl + nf * 2);
                    mma16816(acc[mf][nf], al[mf], bh + nf * 2);
                }
        }
        __syncthreads();
        if (kc + 3 < NCH)
            ffn_load_chunk(kc + 3, sbase + (uint32_t)((kc + 3) & (NSTG - 1)) * STAGE_SZ, stok, e, h0, tid);
        else
            CP_COMMIT();   // keep group count consistent for wait_group 2
    }

    // epilogue: fuse relu(+b1) . w2sum, reduce n within warp, atomicAdd z
    int hb = h0 + warpn * 32 + (lane & 3) * 2;
    float b1v[4][2], wsv[4][2];
#pragma unroll
    for (int nf = 0; nf < 4; nf++) {
        int hc = hb + nf * 8;
        b1v[nf][0] = b1[e * HDIM + hc];     b1v[nf][1] = b1[e * HDIM + hc + 1];
        wsv[nf][0] = g_w2sum[e * HDIM + hc]; wsv[nf][1] = g_w2sum[e * HDIM + hc + 1];
    }
#pragma unroll
    for (int mf = 0; mf < 4; mf++) {
        float z0 = 0.f, z1 = 0.f;
#pragma unroll
        for (int nf = 0; nf < 4; nf++) {
            float v;
            v = acc[mf][nf][0] + b1v[nf][0]; if (v > 0.f) z0 += v * wsv[nf][0];
            v = acc[mf][nf][1] + b1v[nf][1]; if (v > 0.f) z0 += v * wsv[nf][1];
            v = acc[mf][nf][2] + b1v[nf][0]; if (v > 0.f) z1 += v * wsv[nf][0];
            v = acc[mf][nf][3] + b1v[nf][1]; if (v > 0.f) z1 += v * wsv[nf][1];
        }
        z0 += __shfl_xor_sync(0xffffffffu, z0, 1); z0 += __shfl_xor_sync(0xffffffffu, z0, 2);
        z1 += __shfl_xor_sync(0xffffffffu, z1, 1); z1 += __shfl_xor_sync(0xffffffffu, z1, 2);
        if ((lane & 3) == 0) {
            int r = c0 + warpm * 64 + mf * 16 + (lane >> 2);
            if (r < ne)     atomicAdd(&g_z[e * CCAP + r], z0);
            if (r + 8 < ne) atomicAdd(&g_z[e * CCAP + r + 8], z1);
        }
    }
}

// ---------------- combine ----------------------------------------------------
__global__ void combine_kernel() {
    int s = blockIdx.x * blockDim.x + threadIdx.x;
    if (s >= S_TOK) return;
    float v = 0.f;
    int p0 = g_pos0[s];
    if (p0 >= 0) { int e = g_e0[s]; v += g_g0[s] * (g_z[e * CCAP + p0] + g_b2sum[e]); }
    int p1 = g_pos1[s];
    if (p1 >= 0) { int e = g_e1[s]; v += g_g1[s] * (g_z[e * CCAP + p1] + g_b2sum[e]); }
    g_outsum[s] = v;
}

// ---------------- per-batch log_softmax over T ------------------------------
__global__ __launch_bounds__(256) void lsm_kernel(float* __restrict__ out) {
    int b = blockIdx.x, tid = threadIdx.x;
    __shared__ float sh[256];
    const float* v = g_outsum + b * TT;

    float mx = -3.4e38f;
    for (int t = tid; t < TT; t += 256) mx = fmaxf(mx, v[t]);
    sh[tid] = mx; __syncthreads();
    for (int o = 128; o; o >>= 1) { if (tid < o) sh[tid] = fmaxf(sh[tid], sh[tid + o]); __syncthreads(); }
    mx = sh[0]; __syncthreads();

    float sum = 0.f;
    for (int t = tid; t < TT; t += 256) sum += expf(v[t] - mx);
    sh[tid] = sum; __syncthreads();
    for (int o = 128; o; o >>= 1) { if (tid < o) sh[tid] += sh[tid + o]; __syncthreads(); }
    float lse = logf(sh[0]);

    for (int t = tid; t < TT; t += 256) out[b * TT + t] = v[t] - mx - lse;
}

// ---------------- launch -----------------------------------------------------
extern "C" void kernel_launch(void* const* d_in, const int* in_sizes, int n_in,
                              void* d_out, int out_size) {
    const float* x  = (const float*)d_in[0];
    const float* wg = (const float*)d_in[1];
    const float* w1 = (const float*)d_in[2];
    const float* b1 = (const float*)d_in[3];
    const float* w2 = (const float*)d_in[4];
    const float* b2 = (const float*)d_in[5];
    float* out = (float*)d_out;

    route_kernel<<<S_TOK / 8, 256>>>(x, wg);
    cvt_x_kernel<<<(S_TOK * MDIM / 4 + 255) / 256, 256>>>(x);
    cvt_w1t_kernel<<<dim3(HDIM / 32, MDIM / 32, EEXP), dim3(32, 8)>>>(w1);
    w2sum_kernel<<<(EEXP * HDIM) / 8, 256>>>(w2);
    b2sum_kernel<<<1, 256>>>(b2);
    scan_kernel<<<1, 1024>>>();
    zero_z_kernel<<<(EEXP * CCAP) / 256, 256>>>();

    cudaFuncSetAttribute(ffn_kernel, cudaFuncAttributeMaxDynamicSharedMemorySize, FFN_SMEM);
    dim3 g(HDIM / 128, EEXP * (CCAP / 128));
    ffn_kernel<<<g, 256, FFN_SMEM>>>(b1);

    combine_kernel<<<S_TOK / 256, 256>>>();
    lsm_kernel<<<BB, 256>>>(out);
}

// round 8
// speedup vs baseline: 4.8986x; 1.7098x over previous
#include <cuda_runtime.h>
#include <cuda_fp16.h>
#include <cstdint>

#define S_TOK 8192
#define MDIM  1024
#define EEXP  8
#define HDIM  2048
#define CCAP  2048
#define BB    4
#define TT    2048

// ---------------- scratch (device globals; no allocations allowed) ----------
__device__ int   g_e0[S_TOK], g_e1[S_TOK];
__device__ float g_g0[S_TOK], g_g1[S_TOK];
__device__ int   g_pos0[S_TOK], g_pos1[S_TOK];
__device__ int   g_tok[EEXP * CCAP];
__device__ int   g_ne[EEXP];
__device__ float g_w2sum[EEXP * HDIM];
__device__ float g_b2sum[EEXP];
__device__ float g_z[EEXP * CCAP];
__device__ float g_outsum[S_TOK];
// fp16 operands (single-term, 11-bit mantissa)
__device__ __half g_xh[S_TOK * MDIM];
__device__ __half g_w1h[EEXP * MDIM * HDIM];   // native layout [e][m][h]

// ---------------- PTX helpers (family-portable only) -------------------------
__device__ __forceinline__ uint32_t smem_u32(const void* p) {
    uint32_t a;
    asm("{ .reg .u64 t; cvta.to.shared.u64 t, %1; cvt.u32.u64 %0, t; }" : "=r"(a) : "l"(p));
    return a;
}
__device__ __forceinline__ void ldsm4(uint32_t* r, uint32_t addr) {
    asm volatile("ldmatrix.sync.aligned.m8n8.x4.shared.b16 {%0,%1,%2,%3}, [%4];"
                 : "=r"(r[0]), "=r"(r[1]), "=r"(r[2]), "=r"(r[3]) : "r"(addr));
}
__device__ __forceinline__ void ldsm4t(uint32_t* r, uint32_t addr) {
    asm volatile("ldmatrix.sync.aligned.m8n8.x4.trans.shared.b16 {%0,%1,%2,%3}, [%4];"
                 : "=r"(r[0]), "=r"(r[1]), "=r"(r[2]), "=r"(r[3]) : "r"(addr));
}
__device__ __forceinline__ void mma16816(float* c, const uint32_t* a, const uint32_t* b) {
    asm volatile("mma.sync.aligned.m16n8k16.row.col.f32.f16.f16.f32 "
                 "{%0,%1,%2,%3}, {%4,%5,%6,%7}, {%8,%9}, {%0,%1,%2,%3};"
                 : "+f"(c[0]), "+f"(c[1]), "+f"(c[2]), "+f"(c[3])
                 : "r"(a[0]), "r"(a[1]), "r"(a[2]), "r"(a[3]), "r"(b[0]), "r"(b[1]));
}
#define CP_ASYNC16(dst, src, sz) \
    asm volatile("cp.async.cg.shared.global [%0], [%1], 16, %2;" :: "r"(dst), "l"(src), "r"(sz) : "memory")
#define CP_COMMIT() asm volatile("cp.async.commit_group;" ::: "memory")
#define CP_WAIT2()  asm volatile("cp.async.wait_group 2;" ::: "memory")

// ---------------- routing: warp per token (+ fused x -> fp16) ---------------
__global__ __launch_bounds__(256) void route_kernel(const float* __restrict__ x,
                                                    const float* __restrict__ wg) {
    int gwarp = (blockIdx.x * blockDim.x + threadIdx.x) >> 5;
    int lane  = threadIdx.x & 31;
    if (gwarp >= S_TOK) return;
    const float* xr = x + (size_t)gwarp * MDIM;
    __half* xo = g_xh + (size_t)gwarp * MDIM;
    float acc[8];
#pragma unroll
    for (int e = 0; e < 8; e++) acc[e] = 0.f;
    for (int k = lane; k < MDIM; k += 32) {
        float xv = xr[k];
        xo[k] = __float2half(xv);
        const float4* w4 = (const float4*)(wg + (size_t)k * EEXP);
        float4 a = w4[0], b = w4[1];
        acc[0] += xv * a.x; acc[1] += xv * a.y; acc[2] += xv * a.z; acc[3] += xv * a.w;
        acc[4] += xv * b.x; acc[5] += xv * b.y; acc[6] += xv * b.z; acc[7] += xv * b.w;
    }
#pragma unroll
    for (int e = 0; e < 8; e++) {
#pragma unroll
        for (int o = 16; o; o >>= 1) acc[e] += __shfl_xor_sync(0xffffffffu, acc[e], o);
    }
    if (lane == 0) {
        float mx = acc[0];
#pragma unroll
        for (int e = 1; e < 8; e++) mx = fmaxf(mx, acc[e]);
        float p[8]; float den = 0.f;
#pragma unroll
        for (int e = 0; e < 8; e++) { p[e] = expf(acc[e] - mx); den += p[e]; }
#pragma unroll
        for (int e = 0; e < 8; e++) p[e] /= den;
        int i0 = 0; float v0 = p[0];
#pragma unroll
        for (int e = 1; e < 8; e++) if (p[e] > v0) { v0 = p[e]; i0 = e; }
        int i1 = -1; float v1 = -1.f;
#pragma unroll
        for (int e = 0; e < 8; e++) if (e != i0 && p[e] > v1) { v1 = p[e]; i1 = e; }
        float gden = v0 + v1 + 1e-9f;
        g_e0[gwarp] = i0;  g_e1[gwarp] = i1;
        g_g0[gwarp] = v0 / gden;  g_g1[gwarp] = v1 / gden;
    }
}

// ---------------- w1 -> fp16 (elementwise, native layout) -------------------
__global__ __launch_bounds__(256) void cvt_w1h_kernel(const float* __restrict__ w1) {
    int i = blockIdx.x * blockDim.x + threadIdx.x;
    if (i >= EEXP * MDIM * HDIM / 4) return;
    float4 v = ((const float4*)w1)[i];
    __half2* o = (__half2*)g_w1h;
    o[2*i]   = __floats2half2_rn(v.x, v.y);
    o[2*i+1] = __floats2half2_rn(v.z, v.w);
}

// ---------------- w2 row-sum (float4) ---------------------------------------
__global__ __launch_bounds__(256) void w2sum_kernel(const float* __restrict__ w2) {
    int row  = (blockIdx.x * blockDim.x + threadIdx.x) >> 5;
    int lane = threadIdx.x & 31;
    if (row >= EEXP * HDIM) return;
    const float4* p = (const float4*)(w2 + (size_t)row * MDIM);
    float s = 0.f;
#pragma unroll
    for (int i = 0; i < 8; i++) {
        float4 v = p[lane + i * 32];
        s += (v.x + v.y) + (v.z + v.w);
    }
#pragma unroll
    for (int o = 16; o; o >>= 1) s += __shfl_xor_sync(0xffffffffu, s, o);
    if (lane == 0) g_w2sum[row] = s;
}

__global__ void b2sum_kernel(const float* __restrict__ b2) {
    int warp = threadIdx.x >> 5, lane = threadIdx.x & 31;
    if (warp < EEXP) {
        float s = 0.f;
        for (int m = lane; m < MDIM; m += 32) s += b2[warp * MDIM + m];
#pragma unroll
        for (int o = 16; o; o >>= 1) s += __shfl_xor_sync(0xffffffffu, s, o);
        if (lane == 0) g_b2sum[warp] = s;
    }
}

// ---------------- ordered rank / capacity scan (single block, 1024 thr) -----
__global__ __launch_bounds__(1024) void scan_kernel() {
    __shared__ int cnt0[EEXP];
    __shared__ int running[16];
    __shared__ int wcnt[32][16];
    int tid = threadIdx.x, lane = tid & 31, warp = tid >> 5;

    if (tid < EEXP) cnt0[tid] = 0;
    __syncthreads();
    int local[8] = {0,0,0,0,0,0,0,0};
    for (int s = tid; s < S_TOK; s += 1024) {
        int e = g_e0[s];
#pragma unroll
        for (int q = 0; q < 8; q++) local[q] += (e == q);
    }
#pragma unroll
    for (int q = 0; q < 8; q++) if (local[q]) atomicAdd(&cnt0[q], local[q]);
    __syncthreads();
    if (tid < EEXP) { running[tid] = 0; running[8 + tid] = cnt0[tid]; }
    __syncthreads();

    for (int base = 0; base < S_TOK; base += 1024) {
        int s  = base + tid;
        int e0 = g_e0[s], e1 = g_e1[s];
        if (tid < 512) wcnt[tid >> 4][tid & 15] = 0;
        __syncthreads();

        unsigned lt = (1u << lane) - 1u;
        unsigned m0 = __match_any_sync(0xffffffffu, e0);
        int r0 = __popc(m0 & lt);
        if ((m0 & lt) == 0) wcnt[warp][e0] = __popc(m0);
        unsigned m1 = __match_any_sync(0xffffffffu, e1);
        int r1 = __popc(m1 & lt);
        if ((m1 & lt) == 0) wcnt[warp][8 + e1] = __popc(m1);
        __syncthreads();

        int off0 = running[e0];
        int off1 = running[8 + e1];
#pragma unroll
        for (int w = 0; w < 32; w++) {
            if (w < warp) { off0 += wcnt[w][e0]; off1 += wcnt[w][8 + e1]; }
        }
        int pos0 = off0 + r0;
        int pos1 = off1 + r1;
        if (pos0 < CCAP) { g_pos0[s] = pos0; g_tok[e0 * CCAP + pos0] = s; } else g_pos0[s] = -1;
        if (pos1 < CCAP) { g_pos1[s] = pos1; g_tok[e1 * CCAP + pos1] = s; } else g_pos1[s] = -1;
        __syncthreads();
        if (tid < 16) {
            int t = 0;
#pragma unroll
            for (int w = 0; w < 32; w++) t += wcnt[w][tid];
            running[tid] += t;
        }
        __syncthreads();
    }
    if (tid < EEXP) g_ne[tid] = min(running[8 + tid], CCAP);
}

// ---------------- zero z -----------------------------------------------------
__global__ void zero_z_kernel() {
    int i = blockIdx.x * blockDim.x + threadIdx.x;
    if (i < EEXP * CCAP) g_z[i] = 0.f;
}

// ---------------- FFN via mma.sync fp16 (single term) ------------------------
// CTA tile: 128 tok x 128 H, BK = 32, 4-stage cp.async pipeline, 2 CTAs/SM.
// Stage layout: A [0,10240): 128 rows x 80B (64B data + 16 pad)
//               B [10240,18944): 32 k-rows x 272B (256B data + 16 pad), ldmatrix.trans
#define BKC      32
#define NCH      (MDIM / BKC)        // 32
#define AROWB    80
#define BROWB    272
#define A_SZ     (128 * AROWB)       // 10240
#define B_SZ     (BKC * BROWB)       // 8704
#define STAGE_SZ (A_SZ + B_SZ)       // 18944 (128B aligned)
#define NSTG     4
#define FFN_SMEM (NSTG * STAGE_SZ)   // 75776

__device__ __forceinline__ void ffn_load_chunk(int kc, uint32_t stage, const int* stok,
                                               int e, int h0, int tid) {
    int k0 = kc * BKC;
#pragma unroll
    for (int it = 0; it < 4; it++) {
        int id = tid + it * 256;
        uint32_t dst;
        const __half* src;
        int sz = 16;
        if (id < 512) {             // A: 128 rows x 4 x 16B
            int row = id >> 2, seg = id & 3;
            int t = stok[row];
            src = g_xh + ((size_t)(t < 0 ? 0 : t) * MDIM + k0 + seg * 8);
            if (t < 0) sz = 0;
            dst = stage + row * AROWB + seg * 16;
        } else {                    // B: 32 k-rows x 16 x 16B (native w1 layout)
            int b = id - 512;
            int row = b >> 4, seg = b & 15;
            src = g_w1h + ((size_t)(e * MDIM + k0 + row) * HDIM + h0 + seg * 8);
            dst = stage + A_SZ + row * BROWB + seg * 16;
        }
        CP_ASYNC16(dst, src, sz);
    }
    CP_COMMIT();
}

__global__ __launch_bounds__(256, 2) void ffn_kernel(const float* __restrict__ b1) {
    extern __shared__ __align__(128) char smem[];
    __shared__ int stok[128];

    int h0 = blockIdx.x * 128;
    int e  = blockIdx.y >> 4;
    int c0 = (blockIdx.y & 15) * 128;
    int ne = g_ne[e];
    if (c0 >= ne) return;

    int tid = threadIdx.x, wid = tid >> 5, lane = tid & 31;
    int warpm = wid & 1, warpn = wid >> 1;   // 2 x 4 warp grid -> 64m x 32n per warp
    uint32_t sbase = smem_u32(smem);

    if (tid < 128) {
        int c = c0 + tid;
        stok[tid] = (c < ne) ? g_tok[e * CCAP + c] : -1;
    }
    __syncthreads();

    ffn_load_chunk(0, sbase + 0 * STAGE_SZ, stok, e, h0, tid);
    ffn_load_chunk(1, sbase + 1 * STAGE_SZ, stok, e, h0, tid);
    ffn_load_chunk(2, sbase + 2 * STAGE_SZ, stok, e, h0, tid);

    float acc[4][4][4];
#pragma unroll
    for (int i = 0; i < 4; i++)
#pragma unroll
        for (int j = 0; j < 4; j++)
#pragma unroll
            for (int q = 0; q < 4; q++) acc[i][j][q] = 0.f;

    // per-lane ldmatrix offsets
    uint32_t aOff = (uint32_t)((warpm * 64 + (lane & 15)) * AROWB + ((lane >> 4) & 1) * 16);
    uint32_t bOff = (uint32_t)(A_SZ + ((lane & 7) + ((lane >> 3) & 1) * 8) * BROWB
                               + (warpn * 32 + ((lane >> 4) & 1) * 8) * 2);

    for (int kc = 0; kc < NCH; kc++) {
        CP_WAIT2();
        __syncthreads();
        uint32_t stage = sbase + (uint32_t)(kc & (NSTG - 1)) * STAGE_SZ;
#pragma unroll
        for (int ks = 0; ks < 2; ks++) {
            uint32_t ah[4][4], bh[8];
#pragma unroll
            for (int mf = 0; mf < 4; mf++)
                ldsm4(ah[mf], stage + aOff + mf * (16 * AROWB) + ks * 32);
#pragma unroll
            for (int p = 0; p < 2; p++)
                ldsm4t(bh + p * 4, stage + bOff + (uint32_t)(ks * 16) * BROWB + p * 32);
#pragma unroll
            for (int mf = 0; mf < 4; mf++)
#pragma unroll
                for (int nf = 0; nf < 4; nf++)
                    mma16816(acc[mf][nf], ah[mf], bh + nf * 2);
        }
        __syncthreads();
        if (kc + 3 < NCH)
            ffn_load_chunk(kc + 3, sbase + (uint32_t)((kc + 3) & (NSTG - 1)) * STAGE_SZ, stok, e, h0, tid);
        else
            CP_COMMIT();   // keep group count consistent for wait_group 2
    }

    // epilogue: fuse relu(+b1) . w2sum, reduce n within warp, atomicAdd z
    int hb = h0 + warpn * 32 + (lane & 3) * 2;
    float b1v[4][2], wsv[4][2];
#pragma unroll
    for (int nf = 0; nf < 4; nf++) {
        int hc = hb + nf * 8;
        b1v[nf][0] = b1[e * HDIM + hc];     b1v[nf][1] = b1[e * HDIM + hc + 1];
        wsv[nf][0] = g_w2sum[e * HDIM + hc]; wsv[nf][1] = g_w2sum[e * HDIM + hc + 1];
    }
#pragma unroll
    for (int mf = 0; mf < 4; mf++) {
        float z0 = 0.f, z1 = 0.f;
#pragma unroll
        for (int nf = 0; nf < 4; nf++) {
            float v;
            v = acc[mf][nf][0] + b1v[nf][0]; if (v > 0.f) z0 += v * wsv[nf][0];
            v = acc[mf][nf][1] + b1v[nf][1]; if (v > 0.f) z0 += v * wsv[nf][1];
            v = acc[mf][nf][2] + b1v[nf][0]; if (v > 0.f) z1 += v * wsv[nf][0];
            v = acc[mf][nf][3] + b1v[nf][1]; if (v > 0.f) z1 += v * wsv[nf][1];
        }
        z0 += __shfl_xor_sync(0xffffffffu, z0, 1); z0 += __shfl_xor_sync(0xffffffffu, z0, 2);
        z1 += __shfl_xor_sync(0xffffffffu, z1, 1); z1 += __shfl_xor_sync(0xffffffffu, z1, 2);
        if ((lane & 3) == 0) {
            int r = c0 + warpm * 64 + mf * 16 + (lane >> 2);
            if (r < ne)     atomicAdd(&g_z[e * CCAP + r], z0);
            if (r + 8 < ne) atomicAdd(&g_z[e * CCAP + r + 8], z1);
        }
    }
}

// ---------------- combine ----------------------------------------------------
__global__ void combine_kernel() {
    int s = blockIdx.x * blockDim.x + threadIdx.x;
    if (s >= S_TOK) return;
    float v = 0.f;
    int p0 = g_pos0[s];
    if (p0 >= 0) { int e = g_e0[s]; v += g_g0[s] * (g_z[e * CCAP + p0] + g_b2sum[e]); }
    int p1 = g_pos1[s];
    if (p1 >= 0) { int e = g_e1[s]; v += g_g1[s] * (g_z[e * CCAP + p1] + g_b2sum[e]); }
    g_outsum[s] = v;
}

// ---------------- per-batch log_softmax over T ------------------------------
__global__ __launch_bounds__(256) void lsm_kernel(float* __restrict__ out) {
    int b = blockIdx.x, tid = threadIdx.x;
    __shared__ float sh[256];
    const float* v = g_outsum + b * TT;

    float mx = -3.4e38f;
    for (int t = tid; t < TT; t += 256) mx = fmaxf(mx, v[t]);
    sh[tid] = mx; __syncthreads();
    for (int o = 128; o; o >>= 1) { if (tid < o) sh[tid] = fmaxf(sh[tid], sh[tid + o]); __syncthreads(); }
    mx = sh[0]; __syncthreads();

    float sum = 0.f;
    for (int t = tid; t < TT; t += 256) sum += expf(v[t] - mx);
    sh[tid] = sum; __syncthreads();
    for (int o = 128; o; o >>= 1) { if (tid < o) sh[tid] += sh[tid + o]; __syncthreads(); }
    float lse = logf(sh[0]);

    for (int t = tid; t < TT; t += 256) out[b * TT + t] = v[t] - mx - lse;
}

// ---------------- launch -----------------------------------------------------
extern "C" void kernel_launch(void* const* d_in, const int* in_sizes, int n_in,
                              void* d_out, int out_size) {
    const float* x  = (const float*)d_in[0];
    const float* wg = (const float*)d_in[1];
    const float* w1 = (const float*)d_in[2];
    const float* b1 = (const float*)d_in[3];
    const float* w2 = (const float*)d_in[4];
    const float* b2 = (const float*)d_in[5];
    float* out = (float*)d_out;

    route_kernel<<<S_TOK / 8, 256>>>(x, wg);
    cvt_w1h_kernel<<<(EEXP * MDIM * HDIM / 4) / 256, 256>>>(w1);
    w2sum_kernel<<<(EEXP * HDIM) / 8, 256>>>(w2);
    b2sum_kernel<<<1, 256>>>(b2);
    scan_kernel<<<1, 1024>>>();
    zero_z_kernel<<<(EEXP * CCAP) / 256, 256>>>();

    cudaFuncSetAttribute(ffn_kernel, cudaFuncAttributeMaxDynamicSharedMemorySize, FFN_SMEM);
    dim3 g(HDIM / 128, EEXP * (CCAP / 128));
    ffn_kernel<<<g, 256, FFN_SMEM>>>(b1);

    combine_kernel<<<S_TOK / 256, 256>>>();
    lsm_kernel<<<BB, 256>>>(out);
}

// round 9
// speedup vs baseline: 7.6935x; 1.5705x over previous
#include <cuda_runtime.h>
#include <cuda_fp16.h>
#include <cstdint>

#define S_TOK 8192
#define MDIM  1024
#define EEXP  8
#define HDIM  2048
#define CCAP  2048
#define BB    4
#define TT    2048

// ---------------- scratch (device globals; no allocations allowed) ----------
__device__ int   g_e0[S_TOK], g_e1[S_TOK];
__device__ float g_g0[S_TOK], g_g1[S_TOK];
__device__ int   g_pos0[S_TOK], g_pos1[S_TOK];
__device__ int   g_tok[EEXP * CCAP];
__device__ int   g_ne[EEXP];
__device__ float g_w2sum[EEXP * HDIM];
__device__ float g_b2sum[EEXP];
__device__ float g_z[EEXP * CCAP];
// fp16 operands (single-term, 11-bit mantissa)
__device__ __half g_xh[S_TOK * MDIM];
__device__ __half g_w1h[EEXP * MDIM * HDIM];   // native layout [e][m][h]

// ---------------- PTX helpers (family-portable only) -------------------------
__device__ __forceinline__ uint32_t smem_u32(const void* p) {
    uint32_t a;
    asm("{ .reg .u64 t; cvta.to.shared.u64 t, %1; cvt.u32.u64 %0, t; }" : "=r"(a) : "l"(p));
    return a;
}
__device__ __forceinline__ void ldsm4(uint32_t* r, uint32_t addr) {
    asm volatile("ldmatrix.sync.aligned.m8n8.x4.shared.b16 {%0,%1,%2,%3}, [%4];"
                 : "=r"(r[0]), "=r"(r[1]), "=r"(r[2]), "=r"(r[3]) : "r"(addr));
}
__device__ __forceinline__ void ldsm4t(uint32_t* r, uint32_t addr) {
    asm volatile("ldmatrix.sync.aligned.m8n8.x4.trans.shared.b16 {%0,%1,%2,%3}, [%4];"
                 : "=r"(r[0]), "=r"(r[1]), "=r"(r[2]), "=r"(r[3]) : "r"(addr));
}
__device__ __forceinline__ void mma16816(float* c, const uint32_t* a, const uint32_t* b) {
    asm volatile("mma.sync.aligned.m16n8k16.row.col.f32.f16.f16.f32 "
                 "{%0,%1,%2,%3}, {%4,%5,%6,%7}, {%8,%9}, {%0,%1,%2,%3};"
                 : "+f"(c[0]), "+f"(c[1]), "+f"(c[2]), "+f"(c[3])
                 : "r"(a[0]), "r"(a[1]), "r"(a[2]), "r"(a[3]), "r"(b[0]), "r"(b[1]));
}
#define CP_ASYNC16(dst, src, sz) \
    asm volatile("cp.async.cg.shared.global [%0], [%1], 16, %2;" :: "r"(dst), "l"(src), "r"(sz) : "memory")
#define CP_COMMIT() asm volatile("cp.async.commit_group;" ::: "memory")
#define CP_WAIT2()  asm volatile("cp.async.wait_group 2;" ::: "memory")

// ---------------- routing: warp per token (+ fused x -> fp16) ---------------
__global__ __launch_bounds__(256) void route_kernel(const float* __restrict__ x,
                                                    const float* __restrict__ wg) {
    int gwarp = (blockIdx.x * blockDim.x + threadIdx.x) >> 5;
    int lane  = threadIdx.x & 31;
    if (gwarp >= S_TOK) return;
    const float* xr = x + (size_t)gwarp * MDIM;
    __half* xo = g_xh + (size_t)gwarp * MDIM;
    float acc[8];
#pragma unroll
    for (int e = 0; e < 8; e++) acc[e] = 0.f;
    for (int k = lane; k < MDIM; k += 32) {
        float xv = xr[k];
        xo[k] = __float2half(xv);
        const float4* w4 = (const float4*)(wg + (size_t)k * EEXP);
        float4 a = w4[0], b = w4[1];
        acc[0] += xv * a.x; acc[1] += xv * a.y; acc[2] += xv * a.z; acc[3] += xv * a.w;
        acc[4] += xv * b.x; acc[5] += xv * b.y; acc[6] += xv * b.z; acc[7] += xv * b.w;
    }
#pragma unroll
    for (int e = 0; e < 8; e++) {
#pragma unroll
        for (int o = 16; o; o >>= 1) acc[e] += __shfl_xor_sync(0xffffffffu, acc[e], o);
    }
    if (lane == 0) {
        float mx = acc[0];
#pragma unroll
        for (int e = 1; e < 8; e++) mx = fmaxf(mx, acc[e]);
        float p[8]; float den = 0.f;
#pragma unroll
        for (int e = 0; e < 8; e++) { p[e] = expf(acc[e] - mx); den += p[e]; }
#pragma unroll
        for (int e = 0; e < 8; e++) p[e] /= den;
        int i0 = 0; float v0 = p[0];
#pragma unroll
        for (int e = 1; e < 8; e++) if (p[e] > v0) { v0 = p[e]; i0 = e; }
        int i1 = -1; float v1 = -1.f;
#pragma unroll
        for (int e = 0; e < 8; e++) if (e != i0 && p[e] > v1) { v1 = p[e]; i1 = e; }
        float gden = v0 + v1 + 1e-9f;
        g_e0[gwarp] = i0;  g_e1[gwarp] = i1;
        g_g0[gwarp] = v0 / gden;  g_g1[gwarp] = v1 / gden;
    }
}

// ---------------- w1 -> fp16 (elementwise, native layout) -------------------
__global__ __launch_bounds__(256) void cvt_w1h_kernel(const float* __restrict__ w1) {
    int i = blockIdx.x * blockDim.x + threadIdx.x;
    if (i >= EEXP * MDIM * HDIM / 4) return;
    float4 v = ((const float4*)w1)[i];
    __half2* o = (__half2*)g_w1h;
    o[2*i]   = __floats2half2_rn(v.x, v.y);
    o[2*i+1] = __floats2half2_rn(v.z, v.w);
}

// ---------------- w2 row-sum (float4) + fused b2 row-sum --------------------
__global__ __launch_bounds__(256) void w2sum_kernel(const float* __restrict__ w2,
                                                    const float* __restrict__ b2) {
    int lane = threadIdx.x & 31;
    if (blockIdx.x == 2048) {     // fused b2sum
        int warp = threadIdx.x >> 5;
        if (warp < EEXP) {
            float s = 0.f;
            for (int m = lane; m < MDIM; m += 32) s += b2[warp * MDIM + m];
#pragma unroll
            for (int o = 16; o; o >>= 1) s += __shfl_xor_sync(0xffffffffu, s, o);
            if (lane == 0) g_b2sum[warp] = s;
        }
        return;
    }
    int row = (blockIdx.x * blockDim.x + threadIdx.x) >> 5;
    const float4* p = (const float4*)(w2 + (size_t)row * MDIM);
    float s = 0.f;
#pragma unroll
    for (int i = 0; i < 8; i++) {
        float4 v = p[lane + i * 32];
        s += (v.x + v.y) + (v.z + v.w);
    }
#pragma unroll
    for (int o = 16; o; o >>= 1) s += __shfl_xor_sync(0xffffffffu, s, o);
    if (lane == 0) g_w2sum[row] = s;
}

// ---------------- ordered rank / capacity scan (single block, 1024 thr) -----
// Also zeroes g_z at the end (fused zero_z).
__global__ __launch_bounds__(1024) void scan_kernel() {
    __shared__ int cnt0[EEXP];
    __shared__ int running[16];
    __shared__ int wcnt[32][16];
    int tid = threadIdx.x, lane = tid & 31, warp = tid >> 5;

    if (tid < EEXP) cnt0[tid] = 0;
    __syncthreads();
    int local[8] = {0,0,0,0,0,0,0,0};
    for (int s = tid; s < S_TOK; s += 1024) {
        int e = g_e0[s];
#pragma unroll
        for (int q = 0; q < 8; q++) local[q] += (e == q);
    }
#pragma unroll
    for (int q = 0; q < 8; q++) if (local[q]) atomicAdd(&cnt0[q], local[q]);
    __syncthreads();
    if (tid < EEXP) { running[tid] = 0; running[8 + tid] = cnt0[tid]; }
    __syncthreads();

    for (int base = 0; base < S_TOK; base += 1024) {
        int s  = base + tid;
        int e0 = g_e0[s], e1 = g_e1[s];
        if (tid < 512) wcnt[tid >> 4][tid & 15] = 0;
        __syncthreads();

        unsigned lt = (1u << lane) - 1u;
        unsigned m0 = __match_any_sync(0xffffffffu, e0);
        int r0 = __popc(m0 & lt);
        if ((m0 & lt) == 0) wcnt[warp][e0] = __popc(m0);
        unsigned m1 = __match_any_sync(0xffffffffu, e1);
        int r1 = __popc(m1 & lt);
        if ((m1 & lt) == 0) wcnt[warp][8 + e1] = __popc(m1);
        __syncthreads();

        int off0 = running[e0];
        int off1 = running[8 + e1];
#pragma unroll
        for (int w = 0; w < 32; w++) {
            if (w < warp) { off0 += wcnt[w][e0]; off1 += wcnt[w][8 + e1]; }
        }
        int pos0 = off0 + r0;
        int pos1 = off1 + r1;
        if (pos0 < CCAP) { g_pos0[s] = pos0; g_tok[e0 * CCAP + pos0] = s; } else g_pos0[s] = -1;
        if (pos1 < CCAP) { g_pos1[s] = pos1; g_tok[e1 * CCAP + pos1] = s; } else g_pos1[s] = -1;
        __syncthreads();
        if (tid < 16) {
            int t = 0;
#pragma unroll
            for (int w = 0; w < 32; w++) t += wcnt[w][tid];
            running[tid] += t;
        }
        __syncthreads();
    }
    // fused: zero z accumulators
#pragma unroll
    for (int i = 0; i < EEXP * CCAP / 1024; i++) g_z[tid + i * 1024] = 0.f;
    if (tid < EEXP) g_ne[tid] = min(running[8 + tid], CCAP);
}

// ---------------- FFN via mma.sync fp16 (single term) ------------------------
// CTA tile: 128 tok x 128 H, BK = 32, 4-stage cp.async pipeline, 2 CTAs/SM.
// One __syncthreads per chunk; next tile's loads issued BEFORE compute so
// cp.async overlaps the MMAs.
#define BKC      32
#define NCH      (MDIM / BKC)        // 32
#define AROWB    80
#define BROWB    272
#define A_SZ     (128 * AROWB)       // 10240
#define B_SZ     (BKC * BROWB)       // 8704
#define STAGE_SZ (A_SZ + B_SZ)       // 18944
#define NSTG     4
#define FFN_SMEM (NSTG * STAGE_SZ)   // 75776

__device__ __forceinline__ void ffn_load_chunk(int kc, uint32_t stage, const int* stok,
                                               int e, int h0, int tid) {
    int k0 = kc * BKC;
#pragma unroll
    for (int it = 0; it < 4; it++) {
        int id = tid + it * 256;
        uint32_t dst;
        const __half* src;
        int sz = 16;
        if (id < 512) {             // A: 128 rows x 4 x 16B
            int row = id >> 2, seg = id & 3;
            int t = stok[row];
            src = g_xh + ((size_t)(t < 0 ? 0 : t) * MDIM + k0 + seg * 8);
            if (t < 0) sz = 0;
            dst = stage + row * AROWB + seg * 16;
        } else {                    // B: 32 k-rows x 16 x 16B (native w1 layout)
            int b = id - 512;
            int row = b >> 4, seg = b & 15;
            src = g_w1h + ((size_t)(e * MDIM + k0 + row) * HDIM + h0 + seg * 8);
            dst = stage + A_SZ + row * BROWB + seg * 16;
        }
        CP_ASYNC16(dst, src, sz);
    }
    CP_COMMIT();
}

__global__ __launch_bounds__(256, 2) void ffn_kernel(const float* __restrict__ b1) {
    extern __shared__ __align__(128) char smem[];
    __shared__ int stok[128];

    int h0 = blockIdx.x * 128;
    int e  = blockIdx.y >> 4;
    int c0 = (blockIdx.y & 15) * 128;
    int ne = g_ne[e];
    if (c0 >= ne) return;

    int tid = threadIdx.x, wid = tid >> 5, lane = tid & 31;
    int warpm = wid & 1, warpn = wid >> 1;   // 2 x 4 warp grid -> 64m x 32n per warp
    uint32_t sbase = smem_u32(smem);

    if (tid < 128) {
        int c = c0 + tid;
        stok[tid] = (c < ne) ? g_tok[e * CCAP + c] : -1;
    }
    __syncthreads();

    ffn_load_chunk(0, sbase + 0 * STAGE_SZ, stok, e, h0, tid);
    ffn_load_chunk(1, sbase + 1 * STAGE_SZ, stok, e, h0, tid);
    ffn_load_chunk(2, sbase + 2 * STAGE_SZ, stok, e, h0, tid);

    float acc[4][4][4];
#pragma unroll
    for (int i = 0; i < 4; i++)
#pragma unroll
        for (int j = 0; j < 4; j++)
#pragma unroll
            for (int q = 0; q < 4; q++) acc[i][j][q] = 0.f;

    // per-lane ldmatrix offsets
    uint32_t aOff = (uint32_t)((warpm * 64 + (lane & 15)) * AROWB + ((lane >> 4) & 1) * 16);
    uint32_t bOff = (uint32_t)(A_SZ + ((lane & 7) + ((lane >> 3) & 1) * 8) * BROWB
                               + (warpn * 32 + ((lane >> 4) & 1) * 8) * 2);

    for (int kc = 0; kc < NCH; kc++) {
        CP_WAIT2();
        __syncthreads();
        // issue next tile's loads BEFORE compute: overwrites stage (kc-1)&3,
        // which the barrier above just proved everyone finished reading.
        if (kc + 3 < NCH)
            ffn_load_chunk(kc + 3, sbase + (uint32_t)((kc + 3) & (NSTG - 1)) * STAGE_SZ, stok, e, h0, tid);
        else
            CP_COMMIT();   // keep group count consistent for wait_group 2

        uint32_t stage = sbase + (uint32_t)(kc & (NSTG - 1)) * STAGE_SZ;
#pragma unroll
        for (int ks = 0; ks < 2; ks++) {
            uint32_t ah[4][4], bh[8];
#pragma unroll
            for (int mf = 0; mf < 4; mf++)
                ldsm4(ah[mf], stage + aOff + mf * (16 * AROWB) + ks * 32);
#pragma unroll
            for (int p = 0; p < 2; p++)
                ldsm4t(bh + p * 4, stage + bOff + (uint32_t)(ks * 16) * BROWB + p * 32);
#pragma unroll
            for (int mf = 0; mf < 4; mf++)
#pragma unroll
                for (int nf = 0; nf < 4; nf++)
                    mma16816(acc[mf][nf], ah[mf], bh + nf * 2);
        }
    }

    // epilogue: fuse relu(+b1) . w2sum, reduce n within warp, atomicAdd z
    int hb = h0 + warpn * 32 + (lane & 3) * 2;
    float b1v[4][2], wsv[4][2];
#pragma unroll
    for (int nf = 0; nf < 4; nf++) {
        int hc = hb + nf * 8;
        b1v[nf][0] = b1[e * HDIM + hc];     b1v[nf][1] = b1[e * HDIM + hc + 1];
        wsv[nf][0] = g_w2sum[e * HDIM + hc]; wsv[nf][1] = g_w2sum[e * HDIM + hc + 1];
    }
#pragma unroll
    for (int mf = 0; mf < 4; mf++) {
        float z0 = 0.f, z1 = 0.f;
#pragma unroll
        for (int nf = 0; nf < 4; nf++) {
            float v;
            v = acc[mf][nf][0] + b1v[nf][0]; if (v > 0.f) z0 += v * wsv[nf][0];
            v = acc[mf][nf][1] + b1v[nf][1]; if (v > 0.f) z0 += v * wsv[nf][1];
            v = acc[mf][nf][2] + b1v[nf][0]; if (v > 0.f) z1 += v * wsv[nf][0];
            v = acc[mf][nf][3] + b1v[nf][1]; if (v > 0.f) z1 += v * wsv[nf][1];
        }
        z0 += __shfl_xor_sync(0xffffffffu, z0, 1); z0 += __shfl_xor_sync(0xffffffffu, z0, 2);
        z1 += __shfl_xor_sync(0xffffffffu, z1, 1); z1 += __shfl_xor_sync(0xffffffffu, z1, 2);
        if ((lane & 3) == 0) {
            int r = c0 + warpm * 64 + mf * 16 + (lane >> 2);
            if (r < ne)     atomicAdd(&g_z[e * CCAP + r], z0);
            if (r + 8 < ne) atomicAdd(&g_z[e * CCAP + r + 8], z1);
        }
    }
}

// ---------------- fused combine + per-batch log_softmax ---------------------
__global__ __launch_bounds__(1024) void final_kernel(float* __restrict__ out) {
    int b = blockIdx.x, tid = threadIdx.x;
    int lane = tid & 31, wid = tid >> 5;
    __shared__ float sh[32];

    float v[2];
#pragma unroll
    for (int i = 0; i < 2; i++) {
        int s = b * TT + tid + i * 1024;
        float val = 0.f;
        int p0 = g_pos0[s];
        if (p0 >= 0) { int e = g_e0[s]; val += g_g0[s] * (g_z[e * CCAP + p0] + g_b2sum[e]); }
        int p1 = g_pos1[s];
        if (p1 >= 0) { int e = g_e1[s]; val += g_g1[s] * (g_z[e * CCAP + p1] + g_b2sum[e]); }
        v[i] = val;
    }

    // block max
    float mx = fmaxf(v[0], v[1]);
#pragma unroll
    for (int o = 16; o; o >>= 1) mx = fmaxf(mx, __shfl_xor_sync(0xffffffffu, mx, o));
    if (lane == 0) sh[wid] = mx;
    __syncthreads();
    if (wid == 0) {
        float m = sh[lane];
#pragma unroll
        for (int o = 16; o; o >>= 1) m = fmaxf(m, __shfl_xor_sync(0xffffffffu, m, o));
        if (lane == 0) sh[0] = m;
    }
    __syncthreads();
    mx = sh[0];
    __syncthreads();

    // block sum of exp
    float sum = expf(v[0] - mx) + expf(v[1] - mx);
#pragma unroll
    for (int o = 16; o; o >>= 1) sum += __shfl_xor_sync(0xffffffffu, sum, o);
    if (lane == 0) sh[wid] = sum;
    __syncthreads();
    if (wid == 0) {
        float m = sh[lane];
#pragma unroll
        for (int o = 16; o; o >>= 1) m += __shfl_xor_sync(0xffffffffu, m, o);
        if (lane == 0) sh[0] = m;
    }
    __syncthreads();
    float lse = logf(sh[0]);

    out[b * TT + tid]        = v[0] - mx - lse;
    out[b * TT + tid + 1024] = v[1] - mx - lse;
}

// ---------------- launch -----------------------------------------------------
extern "C" void kernel_launch(void* const* d_in, const int* in_sizes, int n_in,
                              void* d_out, int out_size) {
    const float* x  = (const float*)d_in[0];
    const float* wg = (const float*)d_in[1];
    const float* w1 = (const float*)d_in[2];
    const float* b1 = (const float*)d_in[3];
    const float* w2 = (const float*)d_in[4];
    const float* b2 = (const float*)d_in[5];
    float* out = (float*)d_out;

    route_kernel<<<S_TOK / 8, 256>>>(x, wg);
    cvt_w1h_kernel<<<(EEXP * MDIM * HDIM / 4) / 256, 256>>>(w1);
    w2sum_kernel<<<2049, 256>>>(w2, b2);
    scan_kernel<<<1, 1024>>>();

    cudaFuncSetAttribute(ffn_kernel, cudaFuncAttributeMaxDynamicSharedMemorySize, FFN_SMEM);
    dim3 g(HDIM / 128, EEXP * (CCAP / 128));
    ffn_kernel<<<g, 256, FFN_SMEM>>>(b1);

    final_kernel<<<BB, 1024>>>(out);
}